// round 8
// baseline (speedup 1.0000x reference)
#include <cuda_runtime.h>
#include <cuda_fp16.h>
#include <cstdint>

// ---------------------------------------------------------------------------
// HeteroGraph: 2-layer GraphConv (loop + fwd + rev relations) + mean readout.
// Restructured per layer (spmm commutes with dense matmul):
//   GEMM:  Y = act(h)@W0 + (b0+b1+b2) ;  Z1 = act(h)@W1 ; Z2 = act(h)@W2
//   SPMM:  Y[dst] += c*Z1[src] ;  Y[src] += c*Z2[dst]   (c = n_out[s]*n_in[d])
// act = relu for layer>0. Readout applies final relu.
// GEMM: mma.sync fp16, 2-term split (A=hi+lo fp16, B=fp16) fp32 accumulate.
// SPMM: vector red.global.add.v4.f32 scatter.
// ---------------------------------------------------------------------------

#define DIM 128
#define NMAX 500128
#define TILE_M 128

// smem: A_hi 32K | A_lo 32K | B 2x16K | bias 512
#define SM_AHI 0
#define SM_ALO 32768
#define SM_B   65536
#define SM_BIAS 98304
#define GEMM_SMEM (98304 + 512)

// Static scratch
__device__ float g_y[(size_t)NMAX * DIM];
__device__ float g_z1[(size_t)NMAX * DIM];
__device__ float g_z2[(size_t)NMAX * DIM];
__device__ float g_outdeg[NMAX];
__device__ float g_indeg[NMAX];
// Prepacked W^T fp16 images: [layer][group(6)][16KB]; group = 64 output cols
__device__ uint4 g_wpack[2][6][1024];

// ---------------------------------------------------------------------------
__device__ __forceinline__ uint32_t smem_u32(const void* p) {
    uint32_t a;
    asm("{ .reg .u64 t; cvta.to.shared.u64 t, %1; cvt.u32.u64 %0, t; }" : "=r"(a) : "l"(p));
    return a;
}
__device__ __forceinline__ void ldsm4(uint32_t* r, uint32_t addr) {
    asm volatile("ldmatrix.sync.aligned.m8n8.x4.shared.b16 {%0,%1,%2,%3}, [%4];"
                 : "=r"(r[0]), "=r"(r[1]), "=r"(r[2]), "=r"(r[3]) : "r"(addr));
}
__device__ __forceinline__ void mma_fp16(float* d, const uint32_t* a, uint32_t b0, uint32_t b1) {
    asm volatile("mma.sync.aligned.m16n8k16.row.col.f32.f16.f16.f32 "
                 "{%0,%1,%2,%3}, {%4,%5,%6,%7}, {%8,%9}, {%0,%1,%2,%3};"
                 : "+f"(d[0]), "+f"(d[1]), "+f"(d[2]), "+f"(d[3])
                 : "r"(a[0]), "r"(a[1]), "r"(a[2]), "r"(a[3]), "r"(b0), "r"(b1));
}
__device__ __forceinline__ unsigned short h16_bits(float v) {
    __half h = __float2half_rn(v);
    return *(unsigned short*)&h;
}
__device__ __forceinline__ float h16_val(unsigned short b) {
    __half h = *(__half*)&b;
    return __half2float(h);
}

// ---------------------------------------------------------------------------
// Prepack W: image rows = output col n (within 64-col group), 256B of K=128 fp16,
// 16B chunks XOR-swizzled by (n&7).
// ---------------------------------------------------------------------------
__global__ void prepack_kernel(const float* __restrict__ W) {
    int idx = blockIdx.x * blockDim.x + threadIdx.x;   // 2*384*128
    if (idx >= 2 * 384 * 128) return;
    int k = idx & 127;
    int J = (idx >> 7) % 384;
    int l = idx / (384 * 128);
    int r = J >> 7, j = J & 127;
    int g = J >> 6, n = J & 63;
    float v = W[(((size_t)l * 3 + r) * 128 + k) * 128 + j];
    uint32_t off = n * 256 + (((k >> 3) ^ (n & 7)) << 4) + (k & 7) * 2;
    *(unsigned short*)((unsigned char*)&g_wpack[l][g][0] + off) = h16_bits(v);
}

// ---------------------------------------------------------------------------
__global__ void degree_kernel(const int* __restrict__ src, const int* __restrict__ dst,
                              float* odeg, float* ideg, int E) {
    int e = blockIdx.x * blockDim.x + threadIdx.x;
    if (e < E) {
        atomicAdd(&odeg[src[e]], 1.0f);
        atomicAdd(&ideg[dst[e]], 1.0f);
    }
}
__global__ void norm_kernel(float* odeg, float* ideg, int N) {
    int i = blockIdx.x * blockDim.x + threadIdx.x;
    if (i < N) {
        float a = odeg[i]; odeg[i] = (a > 0.0f) ? rsqrtf(a) : 0.0f;
        float b = ideg[i]; ideg[i] = (b > 0.0f) ? rsqrtf(b) : 0.0f;
    }
}

// One warp per edge; both directions; vector red straight into Y.
__global__ void spmm_kernel(const float* __restrict__ z1, const float* __restrict__ z2,
                            const int* __restrict__ src, const int* __restrict__ dst,
                            const float* __restrict__ n_out, const float* __restrict__ n_in,
                            float* __restrict__ y, int E) {
    int e = (blockIdx.x * blockDim.x + threadIdx.x) >> 5;
    if (e >= E) return;
    int lane = threadIdx.x & 31;
    int s = src[e];
    int d = dst[e];
    float c = n_out[s] * n_in[d];
    const float4 zs = *(const float4*)(z1 + (size_t)s * DIM + lane * 4);
    const float4 zd = *(const float4*)(z2 + (size_t)d * DIM + lane * 4);
    float* yd = y + (size_t)d * DIM + lane * 4;
    float* ys = y + (size_t)s * DIM + lane * 4;
    asm volatile("red.global.add.v4.f32 [%0], {%1,%2,%3,%4};"
                 :: "l"(yd), "f"(c * zs.x), "f"(c * zs.y), "f"(c * zs.z), "f"(c * zs.w)
                 : "memory");
    asm volatile("red.global.add.v4.f32 [%0], {%1,%2,%3,%4};"
                 :: "l"(ys), "f"(c * zd.x), "f"(c * zd.y), "f"(c * zd.z), "f"(c * zd.w)
                 : "memory");
}

// ---------------------------------------------------------------------------
// Tensor GEMM: per 128-row tile computes [128,384] = act(X)@[128,384]:
// cols 0-127 -> Y (+bias), 128-255 -> Z1, 256-383 -> Z2.
// 8 warps = 4 mgrp x 2 ngrp, warp tile 32x32, 6 groups of 64 cols.
// fp16 2-term: D = Ahi*B + Alo*B. B double-buffered (register prefetch).
// Y may alias X: each CTA reads only its own 128 rows (converted to smem at
// kernel start) and writes them only in epilogues.
// ---------------------------------------------------------------------------
__global__ __launch_bounds__(256, 2) void gemm3_kernel(
    const float* X, const uint4* __restrict__ wpack,   // [6][1024]
    const float* __restrict__ bl,                      // [3,128]
    float* Y, float* __restrict__ Z1, float* __restrict__ Z2,
    int N, int relu_in)
{
    extern __shared__ char smem[];
    const uint32_t sb = smem_u32(smem);
    const int tid = threadIdx.x;
    const int wid = tid >> 5;
    const int lane = tid & 31;
    const int row0 = blockIdx.x * TILE_M;

    // ---- bias sums ----
    if (tid < 128) {
        *(float*)(smem + SM_BIAS + tid * 4) = bl[tid] + bl[128 + tid] + bl[256 + tid];
    }

    // ---- B group 0 -> registers (overlaps A-fill latency) ----
    uint4 pre[4];
#pragma unroll
    for (int t = 0; t < 4; t++) pre[t] = wpack[tid + t * 256];

    // ---- A fill: 128 rows x 128 k fp32 -> hi/lo fp16, swizzled ----
    {
        const int r = tid >> 1;
        const int khalf = (tid & 1) * 64;
        int grow = row0 + r; if (grow > N - 1) grow = N - 1;
        const float* srcp = X + (size_t)grow * DIM + khalf;
#pragma unroll
        for (int c8 = 0; c8 < 8; c8++) {
            float4 va = *(const float4*)(srcp + c8 * 8);
            float4 vb = *(const float4*)(srcp + c8 * 8 + 4);
            float v[8] = {va.x, va.y, va.z, va.w, vb.x, vb.y, vb.z, vb.w};
            if (relu_in) {
#pragma unroll
                for (int i = 0; i < 8; i++) v[i] = fmaxf(v[i], 0.0f);
            }
            unsigned short hb[8], lb[8];
#pragma unroll
            for (int i = 0; i < 8; i++) {
                hb[i] = h16_bits(v[i]);
                lb[i] = h16_bits(v[i] - h16_val(hb[i]));
            }
            uint4 hq, lq;
            hq.x = (uint32_t)hb[0] | ((uint32_t)hb[1] << 16);
            hq.y = (uint32_t)hb[2] | ((uint32_t)hb[3] << 16);
            hq.z = (uint32_t)hb[4] | ((uint32_t)hb[5] << 16);
            hq.w = (uint32_t)hb[6] | ((uint32_t)hb[7] << 16);
            lq.x = (uint32_t)lb[0] | ((uint32_t)lb[1] << 16);
            lq.y = (uint32_t)lb[2] | ((uint32_t)lb[3] << 16);
            lq.z = (uint32_t)lb[4] | ((uint32_t)lb[5] << 16);
            lq.w = (uint32_t)lb[6] | ((uint32_t)lb[7] << 16);
            int cc = (khalf >> 3) + c8;
            int off = r * 256 + ((cc ^ (r & 7)) << 4);
            *(uint4*)(smem + SM_AHI + off) = hq;
            *(uint4*)(smem + SM_ALO + off) = lq;
        }
    }
    // Stage 0 <- B group 0
    {
        uint4* bdst = (uint4*)(smem + SM_B);
#pragma unroll
        for (int t = 0; t < 4; t++) bdst[tid + t * 256] = pre[t];
    }
    __syncthreads();

    const int mgrp = wid & 3;       // row group (32 rows)
    const int ngrp = wid >> 2;      // col group within 64 (32 cols)

    const int arow[2] = { mgrp * 32 + (lane & 15), mgrp * 32 + 16 + (lane & 15) };
    const int ahi16 = lane >> 4;
    const int brow_base = ngrp * 32 + (lane & 7) + ((lane >> 4) & 1) * 8;
    const int bk = (lane >> 3) & 1;

    const float* bias = (const float*)(smem + SM_BIAS);

#pragma unroll 1
    for (int g = 0; g < 6; g++) {
        // prefetch next B group into registers
        if (g < 5) {
            const uint4* ws = wpack + (size_t)(g + 1) * 1024;
#pragma unroll
            for (int t = 0; t < 4; t++) pre[t] = ws[tid + t * 256];
        }

        const uint32_t bbase = sb + SM_B + (uint32_t)(g & 1) * 16384;

        float acc[2][4][4];
#pragma unroll
        for (int mt = 0; mt < 2; mt++)
#pragma unroll
            for (int nt = 0; nt < 4; nt++)
#pragma unroll
                for (int q = 0; q < 4; q++) acc[mt][nt][q] = 0.0f;

#pragma unroll
        for (int ks = 0; ks < 8; ks++) {
            uint32_t ah[2][4], al[2][4], bh[2][4];
#pragma unroll
            for (int mt = 0; mt < 2; mt++) {
                uint32_t co = ((uint32_t)((ks * 2 + ahi16) ^ (arow[mt] & 7))) << 4;
                ldsm4(ah[mt], sb + SM_AHI + arow[mt] * 256 + co);
                ldsm4(al[mt], sb + SM_ALO + arow[mt] * 256 + co);
            }
#pragma unroll
            for (int h = 0; h < 2; h++) {
                int br = brow_base + h * 16;
                uint32_t co = ((uint32_t)((ks * 2 + bk) ^ (br & 7))) << 4;
                ldsm4(bh[h], bbase + br * 256 + co);
            }
#pragma unroll
            for (int mt = 0; mt < 2; mt++)
#pragma unroll
                for (int nt = 0; nt < 4; nt++) {
                    int h = nt >> 1, p = (nt & 1) * 2;
                    mma_fp16(acc[mt][nt], ah[mt], bh[h][p], bh[h][p + 1]);  // hi*B
                    mma_fp16(acc[mt][nt], al[mt], bh[h][p], bh[h][p + 1]);  // lo*B
                }
        }

        // ---- epilogue for this group ----
        float* outp; int colbase; int with_bias;
        if (g < 2)      { outp = Y;  colbase = g * 64;       with_bias = 1; }
        else if (g < 4) { outp = Z1; colbase = (g - 2) * 64; with_bias = 0; }
        else            { outp = Z2; colbase = (g - 4) * 64; with_bias = 0; }

#pragma unroll
        for (int mt = 0; mt < 2; mt++) {
            int R = row0 + mgrp * 32 + mt * 16 + (lane >> 2);
#pragma unroll
            for (int nt = 0; nt < 4; nt++) {
                int c = colbase + ngrp * 32 + nt * 8 + 2 * (lane & 3);   // 0..126
                float b0 = 0.0f, b1 = 0.0f;
                if (with_bias) {
                    b0 = bias[c];
                    b1 = bias[c + 1];
                }
                if (R < N) {
                    float2 v = make_float2(acc[mt][nt][0] + b0, acc[mt][nt][1] + b1);
                    *(float2*)(outp + (size_t)R * DIM + c) = v;
                }
                if (R + 8 < N) {
                    float2 v = make_float2(acc[mt][nt][2] + b0, acc[mt][nt][3] + b1);
                    *(float2*)(outp + (size_t)(R + 8) * DIM + c) = v;
                }
            }
        }

        // ---- publish prefetched B to the other stage ----
        if (g < 5) {
            uint4* bdst = (uint4*)(smem + SM_B + ((g + 1) & 1) * 16384);
#pragma unroll
            for (int t = 0; t < 4; t++) bdst[tid + t * 256] = pre[t];
        }
        __syncthreads();
    }
}

// ---------------------------------------------------------------------------
// Readout: sorted graph_ids -> block per graph; relu on load; mean.
// ---------------------------------------------------------------------------
__device__ __forceinline__ int lower_bound_i(const int* a, int n, int v) {
    int lo = 0, hi = n;
    while (lo < hi) { int m = (lo + hi) >> 1; if (a[m] < v) lo = m + 1; else hi = m; }
    return lo;
}
__global__ void readout_kernel(const float* __restrict__ h, const int* __restrict__ gid,
                               float* __restrict__ out, int N) {
    int g = blockIdx.x;
    __shared__ int bounds[2];
    if (threadIdx.x == 0) {
        bounds[0] = lower_bound_i(gid, N, g);
        bounds[1] = lower_bound_i(gid, N, g + 1);
    }
    __syncthreads();
    int lo = bounds[0], hi = bounds[1];
    float s = 0.0f;
    for (int r = lo; r < hi; r++)
        s += fmaxf(h[(size_t)r * DIM + threadIdx.x], 0.0f);
    float cnt = (float)(hi - lo);
    out[(size_t)g * DIM + threadIdx.x] = s / fmaxf(cnt, 1.0f);
}

// ---------------------------------------------------------------------------
extern "C" void kernel_launch(void* const* d_in, const int* in_sizes, int n_in,
                              void* d_out, int out_size) {
    const float* feat = (const float*)d_in[0];   // [N,128]
    const float* W    = (const float*)d_in[1];   // [2,3,128,128]
    const float* b    = (const float*)d_in[2];   // [2,3,128]
    const int*   esrc = (const int*)d_in[3];     // [E]
    const int*   edst = (const int*)d_in[4];     // [E]
    const int*   gids = (const int*)d_in[5];     // [N] sorted

    const int N = in_sizes[0] / DIM;
    const int E = in_sizes[3];
    const int G = out_size / DIM;

    float *y, *z1, *z2, *odeg, *ideg;
    uint4* wp;
    cudaGetSymbolAddress((void**)&y,    g_y);
    cudaGetSymbolAddress((void**)&z1,   g_z1);
    cudaGetSymbolAddress((void**)&z2,   g_z2);
    cudaGetSymbolAddress((void**)&odeg, g_outdeg);
    cudaGetSymbolAddress((void**)&ideg, g_indeg);
    cudaGetSymbolAddress((void**)&wp,   g_wpack);

    cudaFuncSetAttribute(gemm3_kernel,
                         cudaFuncAttributeMaxDynamicSharedMemorySize, GEMM_SMEM);

    prepack_kernel<<<(2 * 384 * 128 + 255) / 256, 256>>>(W);

    cudaMemsetAsync(odeg, 0, (size_t)N * sizeof(float));
    cudaMemsetAsync(ideg, 0, (size_t)N * sizeof(float));
    degree_kernel<<<(E + 255) / 256, 256>>>(esrc, edst, odeg, ideg, E);
    norm_kernel<<<(N + 255) / 256, 256>>>(odeg, ideg, N);

    const int tiles = (N + TILE_M - 1) / TILE_M;
    const int spmm_blocks = (int)(((long long)E * 32 + 255) / 256);
    const float* hin = feat;
    for (int l = 0; l < 2; l++) {
        gemm3_kernel<<<tiles, 256, GEMM_SMEM>>>(
            hin, wp + (size_t)l * 6 * 1024, b + (size_t)l * 3 * 128,
            y, z1, z2, N, l > 0 ? 1 : 0);
        spmm_kernel<<<spmm_blocks, 256>>>(z1, z2, esrc, edst, odeg, ideg, y, E);
        hin = y;
    }

    readout_kernel<<<G, DIM>>>(y, gids, (float*)d_out, N);
}